// round 15
// baseline (speedup 1.0000x reference)
#include <cuda_runtime.h>
#include <math.h>

#define DD    512
#define HH    256
#define G4    1024
#define NT    128
#define NB    5
#define NEP   1024
#define M640  640      // NT*NB
#define SCTA  64       // scan CTAs (32 per direction)

// ---------- static device scratch (no allocation) ----------
__device__ __align__(16) float g_v[DD];
__device__ float g_c0;
__device__ __align__(16) float g_scores[NEP];
__device__ int   g_idx[8];
__device__ float g_wsel[8];
__device__ __align__(16) float g_x1 [M640 * DD];       // layer-0 output
__device__ __align__(16) float g_lout[M640 * DD];      // layer-1 output
__device__ __align__(16) float g_pre[2 * M640 * G4];   // pre-gates [dir][m][j]
// tagged h exchange: [phase][dir][parity][b][elem] = {h, tag}; tag = step+1 (never 0)
__device__ __align__(16) float2 g_hx[2][2][2][NB][HH];
__device__ unsigned g_done;    // scores->topk last-block counter (self-resetting)

// ---------- helpers ----------
union F2U { float2 f; unsigned long long u; };
__device__ __forceinline__ float2 f2fma(float2 a, float2 b, float2 c) {
    F2U A, B, C, Dv; A.f = a; B.f = b; C.f = c;
    asm("fma.rn.f32x2 %0, %1, %2, %3;" : "=l"(Dv.u) : "l"(A.u), "l"(B.u), "l"(C.u));
    return Dv.f;
}
__device__ __forceinline__ float fast_tanh(float x) {
    float r; asm("tanh.approx.f32 %0, %1;" : "=f"(r) : "f"(x)); return r;
}
__device__ __forceinline__ float fast_sigmoid(float x) {
    return __fdividef(1.f, 1.f + __expf(-x));
}
__device__ __forceinline__ float2 ld_vol_f2(const float2* p) {
    float2 v;
    asm volatile("ld.volatile.global.v2.f32 {%0,%1}, [%2];"
                 : "=f"(v.x), "=f"(v.y) : "l"(p) : "memory");
    return v;
}
__device__ __forceinline__ void st_vol_f2(float2* p, float h, float tag) {
    asm volatile("st.volatile.global.v2.f32 [%0], {%1,%2};"
                 :: "l"(p), "f"(h), "f"(tag) : "memory");
}

// ---------------- qp = Wq@q + bq ; v = Wk^T@qp ; c0 = bk.qp ----------------
__global__ void k_prep(const float* __restrict__ query, const float* __restrict__ Wq,
                       const float* __restrict__ bq, const float* __restrict__ Wk,
                       const float* __restrict__ bk) {
    __shared__ float qs[DD], qps[DD], red[DD];
    int tid = threadIdx.x;
    qs[tid] = query[tid];
    __syncthreads();
    const float* wr = Wq + (size_t)tid * DD;
    float s = bq[tid];
#pragma unroll 8
    for (int d = 0; d < DD; d++) s += wr[d] * qs[d];
    qps[tid] = s;
    __syncthreads();
    float vv = 0.f;
#pragma unroll 8
    for (int e = 0; e < DD; e++) vv += Wk[(size_t)e * DD + tid] * qps[e];
    g_v[tid] = vv;
    red[tid] = bk[tid] * qps[tid];
    __syncthreads();
    for (int st = 256; st > 0; st >>= 1) {
        if (tid < st) red[tid] += red[tid + st];
        __syncthreads();
    }
    if (tid == 0) g_c0 = red[0];
}

// ---------------- fused scores + top-5 (last block does topk) ----------------
__global__ void __launch_bounds__(256) k_scores_topk(const float* __restrict__ ep,
                                                     const float* __restrict__ ages) {
    __shared__ float4 vs[DD / 4];
    __shared__ float sred[256];
    __shared__ int s_last;
    int tid = threadIdx.x;
    if (tid < 128) vs[tid] = ((const float4*)g_v)[tid];
    __syncthreads();
    const float4* e4 = (const float4*)ep + (size_t)blockIdx.x * (NT * DD / 4);
    float acc = 0.f;
#pragma unroll 4
    for (int it = 0; it < 64; it++) {
        int i = tid + 256 * it;
        float4 x = e4[i];
        float4 w = vs[i & 127];
        acc += x.x * w.x + x.y * w.y + x.z * w.z + x.w * w.w;
    }
    sred[tid] = acc;
    __syncthreads();
    for (int st = 128; st > 0; st >>= 1) {
        if (tid < st) sred[tid] += sred[tid + st];
        __syncthreads();
    }
    if (tid == 0) {
        g_scores[blockIdx.x] = sred[0] * (1.0f / NT) + g_c0;
        __threadfence();
        unsigned old = atomicAdd(&g_done, 1u);
        s_last = (old == NEP - 1u) ? 1 : 0;
    }
    __syncthreads();
    if (!s_last) return;

    __shared__ float sc[NEP];
    __shared__ float wv_[8];
    __shared__ int   wi_[8];
    int lane = tid & 31, wid = tid >> 5;
    __threadfence();
    for (int i = tid; i < NEP; i += 256) sc[i] = g_scores[i];
    __syncthreads();
    for (int r = 0; r < NB; r++) {
        float bv = -INFINITY; int bi = 0x7fffffff;
        for (int i = tid; i < NEP; i += 256) {
            float v = sc[i];
            if (v > bv || (v == bv && i < bi)) { bv = v; bi = i; }
        }
#pragma unroll
        for (int off = 16; off; off >>= 1) {
            float ov = __shfl_down_sync(0xffffffffu, bv, off);
            int   oi = __shfl_down_sync(0xffffffffu, bi, off);
            if (ov > bv || (ov == bv && oi < bi)) { bv = ov; bi = oi; }
        }
        if (lane == 0) { wv_[wid] = bv; wi_[wid] = bi; }
        __syncthreads();
        if (tid < 8) {
            bv = wv_[tid]; bi = wi_[tid];
#pragma unroll
            for (int off = 4; off; off >>= 1) {
                float ov = __shfl_down_sync(0xffu, bv, off);
                int   oi = __shfl_down_sync(0xffu, bi, off);
                if (ov > bv || (ov == bv && oi < bi)) { bv = ov; bi = oi; }
            }
            if (tid == 0) {
                g_idx[r]  = bi;
                g_wsel[r] = 1.f / (1.f + ages[bi] * 0.01f);
                sc[bi] = -INFINITY;
            }
        }
        __syncthreads();
    }
    if (tid == 0) g_done = 0u;                 // self-reset for graph replay
}

// ---------------- pre-gate GEMM (f32x2); phase 0 fuses the gather ----------------
__global__ void __launch_bounds__(256) k_gemm(int phase, const float* __restrict__ ep,
        const float* __restrict__ B0, const float* __restrict__ bi0, const float* __restrict__ bh0,
        const float* __restrict__ B1, const float* __restrict__ bi1, const float* __restrict__ bh1) {
    int dir = blockIdx.z;
    const float* B  = dir ? B1  : B0;
    const float* bi = dir ? bi1 : bi0;
    const float* bh = dir ? bh1 : bh0;
    float* C = g_pre + (size_t)dir * M640 * G4;

    __shared__ __align__(16) float As[16][68];
    __shared__ __align__(16) float Bs[16][68];

    int tid = threadIdx.x;
    int m0 = blockIdx.y * 64, n0 = blockIdx.x * 64;
    int tx = tid & 15, ty = tid >> 4;
    float2 accL[4], accH[4];
#pragma unroll
    for (int i = 0; i < 4; i++) { accL[i] = make_float2(0.f, 0.f); accH[i] = make_float2(0.f, 0.f); }

    int ml = tid >> 2, kl = (tid & 3) << 2;
    const float* Ag;
    float sA = 1.f;
    {
        int m = m0 + ml;
        if (phase) {
            Ag = g_x1 + (size_t)m * DD + kl;
        } else {
            int t = m / NB, b = m - NB * t;
            Ag = ep + ((size_t)g_idx[b] * NT + t) * DD + kl;
            sA = g_wsel[b];
        }
    }
    const float* Bg = B + (size_t)(n0 + ml) * DD + kl;

    for (int k0 = 0; k0 < DD; k0 += 16) {
        float4 av = *(const float4*)(Ag + k0);
        float4 bv = *(const float4*)(Bg + k0);
        av.x *= sA; av.y *= sA; av.z *= sA; av.w *= sA;
        As[kl + 0][ml] = av.x; As[kl + 1][ml] = av.y; As[kl + 2][ml] = av.z; As[kl + 3][ml] = av.w;
        Bs[kl + 0][ml] = bv.x; Bs[kl + 1][ml] = bv.y; Bs[kl + 2][ml] = bv.z; Bs[kl + 3][ml] = bv.w;
        __syncthreads();
#pragma unroll
        for (int kk = 0; kk < 16; kk++) {
            float4 a = *(const float4*)&As[kk][ty << 2];
            float4 b = *(const float4*)&Bs[kk][tx << 2];
            float2 b01 = make_float2(b.x, b.y), b23 = make_float2(b.z, b.w);
            float aa[4] = { a.x, a.y, a.z, a.w };
#pragma unroll
            for (int i = 0; i < 4; i++) {
                float2 ad = make_float2(aa[i], aa[i]);
                accL[i] = f2fma(ad, b01, accL[i]);
                accH[i] = f2fma(ad, b23, accH[i]);
            }
        }
        __syncthreads();
    }
#pragma unroll
    for (int i = 0; i < 4; i++) {
        int m = m0 + (ty << 2) + i;
        int n = n0 + (tx << 2);
        float4 o;
        o.x = accL[i].x + bi[n + 0] + bh[n + 0];
        o.y = accL[i].y + bi[n + 1] + bh[n + 1];
        o.z = accH[i].x + bi[n + 2] + bh[n + 2];
        o.w = accH[i].y + bi[n + 3] + bh[n + 3];
        *(float4*)&C[(size_t)m * G4 + n] = o;
    }
}

// ---------------- bidirectional LSTM scan: tagged data-flow sync + poll backoff ----------------
// 64 persistent CTAs x 256 thr; CTA owns 8 hidden units (32 gate rows).
// warp = h-segment, lane = gate row, w_hh in registers.
// h exchange: {h, tag=s+1} as atomic 8B volatile stores; consumers poll
// their own element (x5 batches) until tag matches, with nanosleep backoff
// to avoid saturating LTS with the poll storm. Double-buffered by parity.
__global__ void __launch_bounds__(256) k_scan(int phase,
        const float* __restrict__ whf, const float* __restrict__ whb) {
    float* out = phase ? g_lout : g_x1;
    int cta = blockIdx.x;
    int dir = cta >> 5;
    int gidx = cta & 31;
    int hbase = gidx * 8;
    const float* whh  = dir ? whb : whf;
    const float* preb = g_pre + (size_t)dir * M640 * G4;
    float2* hx = &g_hx[phase][dir][0][0][0];   // [parity][b][elem]

    int tid  = threadIdx.x;
    int wsg  = tid >> 5;     // h-segment 0..7
    int lane = tid & 31;     // gate row 0..31
    int jrow = (lane >> 3) * HH + hbase + (lane & 7);

    float2 wreg[16];
    {
        const float2* wr = (const float2*)(whh + (size_t)jrow * HH + wsg * 32);
#pragma unroll
        for (int i = 0; i < 16; i++) wreg[i] = wr[i];
    }

    __shared__ __align__(16) float hsp[NB][HH];  // staged h_{t-1}
    __shared__ float red [8][32][NB];
    __shared__ float garr[32][NB];

    int rr5 = tid / NB, b5 = tid - rr5 * NB;              // reduce role (tid<160)
    int jred = (rr5 >> 3) * HH + hbase + (rr5 & 7);
    int u8 = tid / NB, b8 = tid - u8 * NB;                // activation role (tid<40)
    int hg = hbase + u8;
    float cstate = 0.f;

    for (int s = 0; s < NT; s++) {
        int t = dir ? (NT - 1 - s) : s;

        // prefetch pre-gate (overlaps poll + matvec)
        float prev = 0.f;
        if (tid < 32 * NB) prev = __ldg(&preb[((size_t)t * NB + b5) * G4 + jred]);

        float2 acc[NB];
#pragma unroll
        for (int b = 0; b < NB; b++) acc[b] = make_float2(0.f, 0.f);

        if (s > 0) {
            // poll own element (x5 batches) until tag == s; nanosleep backoff
            // keeps poll traffic well under the LTS ceiling so producers'
            // stores stay fast.
            const float2* hb = hx + ((s - 1) & 1) * (NB * HH) + tid;
            float tagf = (float)s;
            float2 v0, v1, v2, v3, v4;
            v0 = ld_vol_f2(hb + 0 * HH);
            v1 = ld_vol_f2(hb + 1 * HH);
            v2 = ld_vol_f2(hb + 2 * HH);
            v3 = ld_vol_f2(hb + 3 * HH);
            v4 = ld_vol_f2(hb + 4 * HH);
            while (!(v0.y == tagf && v1.y == tagf && v2.y == tagf &&
                     v3.y == tagf && v4.y == tagf)) {
                __nanosleep(40);
                v0 = ld_vol_f2(hb + 0 * HH);
                v1 = ld_vol_f2(hb + 1 * HH);
                v2 = ld_vol_f2(hb + 2 * HH);
                v3 = ld_vol_f2(hb + 3 * HH);
                v4 = ld_vol_f2(hb + 4 * HH);
            }
            hsp[0][tid] = v0.x; hsp[1][tid] = v1.x; hsp[2][tid] = v2.x;
            hsp[3][tid] = v3.x; hsp[4][tid] = v4.x;
            __syncwarp();   // warp wsg's matvec uses exactly elements [32*wsg, +32)

#pragma unroll
            for (int i4 = 0; i4 < 8; i4++) {
                float2 w0 = wreg[2 * i4], w1 = wreg[2 * i4 + 1];
#pragma unroll
                for (int b = 0; b < NB; b++) {
                    float4 h = *(const float4*)&hsp[b][(wsg << 5) + (i4 << 2)]; // broadcast
                    acc[b] = f2fma(w0, make_float2(h.x, h.y), acc[b]);
                    acc[b] = f2fma(w1, make_float2(h.z, h.w), acc[b]);
                }
            }
        }
#pragma unroll
        for (int b = 0; b < NB; b++) red[wsg][lane][b] = acc[b].x + acc[b].y;
        __syncthreads();

        if (tid < 32 * NB) {
            float ssum = prev;
#pragma unroll
            for (int q = 0; q < 8; q++) ssum += red[q][rr5][b5];
            garr[rr5][b5] = ssum;
        }
        __syncthreads();

        if (tid < 8 * NB) {
            float ig = garr[u8][b8];
            float fg = garr[8 + u8][b8];
            float cg = garr[16 + u8][b8];
            float og = garr[24 + u8][b8];
            float si = fast_sigmoid(ig);
            float sf = fast_sigmoid(fg);
            float so = fast_sigmoid(og);
            cstate = sf * cstate + si * fast_tanh(cg);
            float hv = so * fast_tanh(cstate);
            out[((size_t)t * NB + b8) * DD + dir * HH + hg] = hv;
            if (s < NT - 1)
                st_vol_f2(hx + (s & 1) * (NB * HH) + b8 * HH + hg, hv, (float)(s + 1));
        }
        // no trailing barrier needed: the next __syncthreads() (after red)
        // orders act's garr reads before the following reduce's garr writes.
    }
}

// ---------------- attention + softmax + context ----------------
__global__ void k_attn(const float* __restrict__ cs, float* __restrict__ outp) {
    __shared__ __align__(16) float css[DD];
    __shared__ float aw[NT];
    __shared__ float r1[NT];
    int b = blockIdx.x, tid = threadIdx.x;
    ((float4*)css)[tid] = ((const float4*)cs)[tid];
    __syncthreads();

    const float4* lb = (const float4*)(g_lout + ((size_t)tid * NB + b) * DD);
    float att = 0.f;
#pragma unroll 4
    for (int i = 0; i < DD / 4; i++) {
        float4 x = lb[i];
        float4 c = ((float4*)css)[i];
        att += x.x * c.x + x.y * c.y + x.z * c.z + x.w * c.w;
    }
    r1[tid] = att;
    __syncthreads();
    for (int st = 64; st > 0; st >>= 1) {
        if (tid < st) r1[tid] = fmaxf(r1[tid], r1[tid + st]);
        __syncthreads();
    }
    float mx = r1[0];
    __syncthreads();
    float e = expf(att - mx);
    r1[tid] = e;
    __syncthreads();
    for (int st = 64; st > 0; st >>= 1) {
        if (tid < st) r1[tid] += r1[tid + st];
        __syncthreads();
    }
    float inv = 1.f / r1[0];
    __syncthreads();
    aw[tid] = e * inv;
    __syncthreads();

    float4 ctx = make_float4(0.f, 0.f, 0.f, 0.f);
    for (int l = 0; l < NT; l++) {
        float wv = aw[l];
        float4 x = *(const float4*)(g_lout + ((size_t)l * NB + b) * DD + (tid << 2));
        ctx.x += wv * x.x; ctx.y += wv * x.y; ctx.z += wv * x.z; ctx.w += wv * x.w;
    }
    *(float4*)(outp + (size_t)b * DD + (tid << 2)) = ctx;
}

// ---------------- launcher (scan0 is launch #4 -> ncu captures it) ----------------
extern "C" void kernel_launch(void* const* d_in, const int* in_sizes, int n_in,
                              void* d_out, int out_size) {
    const float* episodes = (const float*)d_in[0];
    const float* query    = (const float*)d_in[1];
    const float* cstate   = (const float*)d_in[2];
    const float* ages     = (const float*)d_in[3];
    const float* Wq = (const float*)d_in[4];
    const float* bq = (const float*)d_in[5];
    const float* Wk = (const float*)d_in[6];
    const float* bk = (const float*)d_in[7];
    const float* w_ih_l0  = (const float*)d_in[8];
    const float* w_hh_l0  = (const float*)d_in[9];
    const float* b_ih_l0  = (const float*)d_in[10];
    const float* b_hh_l0  = (const float*)d_in[11];
    const float* w_ih_l0r = (const float*)d_in[12];
    const float* w_hh_l0r = (const float*)d_in[13];
    const float* b_ih_l0r = (const float*)d_in[14];
    const float* b_hh_l0r = (const float*)d_in[15];
    const float* w_ih_l1  = (const float*)d_in[16];
    const float* w_hh_l1  = (const float*)d_in[17];
    const float* b_ih_l1  = (const float*)d_in[18];
    const float* b_hh_l1  = (const float*)d_in[19];
    const float* w_ih_l1r = (const float*)d_in[20];
    const float* w_hh_l1r = (const float*)d_in[21];
    const float* b_ih_l1r = (const float*)d_in[22];
    const float* b_hh_l1r = (const float*)d_in[23];
    float* out = (float*)d_out;

    k_prep       <<<1, 512>>>(query, Wq, bq, Wk, bk);                     // 1
    k_scores_topk<<<NEP, 256>>>(episodes, ages);                          // 2
    k_gemm<<<dim3(16, 10, 2), 256>>>(0, episodes,                         // 3
                                     w_ih_l0, b_ih_l0, b_hh_l0,
                                     w_ih_l0r, b_ih_l0r, b_hh_l0r);
    k_scan<<<SCTA, 256>>>(0, w_hh_l0, w_hh_l0r);                          // 4 <- ncu capture
    k_gemm<<<dim3(16, 10, 2), 256>>>(1, episodes,                         // 5
                                     w_ih_l1, b_ih_l1, b_hh_l1,
                                     w_ih_l1r, b_ih_l1r, b_hh_l1r);
    k_scan<<<SCTA, 256>>>(1, w_hh_l1, w_hh_l1r);                          // 6
    k_attn<<<NB, 128>>>(cstate, out);                                     // 7
}

// round 16
// speedup vs baseline: 1.0852x; 1.0852x over previous
#include <cuda_runtime.h>
#include <math.h>

#define DD    512
#define HH    256
#define G4    1024
#define NT    128
#define NB    5
#define NEP   1024
#define M640  640      // NT*NB
#define SCTA  64       // scan CTAs (32 per direction)

// ---------- static device scratch (no allocation) ----------
__device__ __align__(16) float g_v[DD];
__device__ float g_c0;
__device__ __align__(16) float g_scores[NEP];
__device__ int   g_idx[8];
__device__ float g_wsel[8];
__device__ __align__(16) float g_x1 [M640 * DD];       // layer-0 output
__device__ __align__(16) float g_lout[M640 * DD];      // layer-1 output
__device__ __align__(16) float g_pre[2 * M640 * G4];   // pre-gates [dir][m][j]
// tagged h exchange: [phase][dir][parity][b][elem] = {h, tag}; tag = step+1 (never 0)
__device__ __align__(16) float2 g_hx[2][2][2][NB][HH];
__device__ unsigned g_done;    // scores->topk last-block counter (self-resetting)

// ---------- helpers ----------
union F2U { float2 f; unsigned long long u; };
__device__ __forceinline__ float2 f2fma(float2 a, float2 b, float2 c) {
    F2U A, B, C, Dv; A.f = a; B.f = b; C.f = c;
    asm("fma.rn.f32x2 %0, %1, %2, %3;" : "=l"(Dv.u) : "l"(A.u), "l"(B.u), "l"(C.u));
    return Dv.f;
}
__device__ __forceinline__ float fast_tanh(float x) {
    float r; asm("tanh.approx.f32 %0, %1;" : "=f"(r) : "f"(x)); return r;
}
// sigmoid(x) = 0.5*tanh(0.5x) + 0.5  (one MUFU instead of EX2+RCP chain)
__device__ __forceinline__ float fast_sigmoid(float x) {
    return fmaf(0.5f, fast_tanh(0.5f * x), 0.5f);
}
__device__ __forceinline__ float2 ld_vol_f2(const float2* p) {
    float2 v;
    asm volatile("ld.volatile.global.v2.f32 {%0,%1}, [%2];"
                 : "=f"(v.x), "=f"(v.y) : "l"(p) : "memory");
    return v;
}
__device__ __forceinline__ void st_vol_f2(float2* p, float h, float tag) {
    asm volatile("st.volatile.global.v2.f32 [%0], {%1,%2};"
                 :: "l"(p), "f"(h), "f"(tag) : "memory");
}

// ---------------- qp = Wq@q + bq ; v = Wk^T@qp ; c0 = bk.qp ----------------
__global__ void k_prep(const float* __restrict__ query, const float* __restrict__ Wq,
                       const float* __restrict__ bq, const float* __restrict__ Wk,
                       const float* __restrict__ bk) {
    __shared__ float qs[DD], qps[DD], red[DD];
    int tid = threadIdx.x;
    qs[tid] = query[tid];
    __syncthreads();
    const float* wr = Wq + (size_t)tid * DD;
    float s = bq[tid];
#pragma unroll 8
    for (int d = 0; d < DD; d++) s += wr[d] * qs[d];
    qps[tid] = s;
    __syncthreads();
    float vv = 0.f;
#pragma unroll 8
    for (int e = 0; e < DD; e++) vv += Wk[(size_t)e * DD + tid] * qps[e];
    g_v[tid] = vv;
    red[tid] = bk[tid] * qps[tid];
    __syncthreads();
    for (int st = 256; st > 0; st >>= 1) {
        if (tid < st) red[tid] += red[tid + st];
        __syncthreads();
    }
    if (tid == 0) g_c0 = red[0];
}

// ---------------- fused scores + top-5 (last block does topk) ----------------
__global__ void __launch_bounds__(256) k_scores_topk(const float* __restrict__ ep,
                                                     const float* __restrict__ ages) {
    __shared__ float4 vs[DD / 4];
    __shared__ float sred[256];
    __shared__ int s_last;
    int tid = threadIdx.x;
    if (tid < 128) vs[tid] = ((const float4*)g_v)[tid];
    __syncthreads();
    const float4* e4 = (const float4*)ep + (size_t)blockIdx.x * (NT * DD / 4);
    float acc = 0.f;
#pragma unroll 4
    for (int it = 0; it < 64; it++) {
        int i = tid + 256 * it;
        float4 x = e4[i];
        float4 w = vs[i & 127];
        acc += x.x * w.x + x.y * w.y + x.z * w.z + x.w * w.w;
    }
    sred[tid] = acc;
    __syncthreads();
    for (int st = 128; st > 0; st >>= 1) {
        if (tid < st) sred[tid] += sred[tid + st];
        __syncthreads();
    }
    if (tid == 0) {
        g_scores[blockIdx.x] = sred[0] * (1.0f / NT) + g_c0;
        __threadfence();
        unsigned old = atomicAdd(&g_done, 1u);
        s_last = (old == NEP - 1u) ? 1 : 0;
    }
    __syncthreads();
    if (!s_last) return;

    __shared__ float sc[NEP];
    __shared__ float wv_[8];
    __shared__ int   wi_[8];
    int lane = tid & 31, wid = tid >> 5;
    __threadfence();
    for (int i = tid; i < NEP; i += 256) sc[i] = g_scores[i];
    __syncthreads();
    for (int r = 0; r < NB; r++) {
        float bv = -INFINITY; int bi = 0x7fffffff;
        for (int i = tid; i < NEP; i += 256) {
            float v = sc[i];
            if (v > bv || (v == bv && i < bi)) { bv = v; bi = i; }
        }
#pragma unroll
        for (int off = 16; off; off >>= 1) {
            float ov = __shfl_down_sync(0xffffffffu, bv, off);
            int   oi = __shfl_down_sync(0xffffffffu, bi, off);
            if (ov > bv || (ov == bv && oi < bi)) { bv = ov; bi = oi; }
        }
        if (lane == 0) { wv_[wid] = bv; wi_[wid] = bi; }
        __syncthreads();
        if (tid < 8) {
            bv = wv_[tid]; bi = wi_[tid];
#pragma unroll
            for (int off = 4; off; off >>= 1) {
                float ov = __shfl_down_sync(0xffu, bv, off);
                int   oi = __shfl_down_sync(0xffu, bi, off);
                if (ov > bv || (ov == bv && oi < bi)) { bv = ov; bi = oi; }
            }
            if (tid == 0) {
                g_idx[r]  = bi;
                g_wsel[r] = 1.f / (1.f + ages[bi] * 0.01f);
                sc[bi] = -INFINITY;
            }
        }
        __syncthreads();
    }
    if (tid == 0) g_done = 0u;                 // self-reset for graph replay
}

// ---------------- pre-gate GEMM: 128x64 tile, 8x4/thread, reg-prefetch pipeline ----
// grid (16 nTiles, 5 mTiles, 2 dir) x 256. phase 0 fuses the episode gather+scale.
__global__ void __launch_bounds__(256) k_gemm(int phase, const float* __restrict__ ep,
        const float* __restrict__ B0, const float* __restrict__ bi0, const float* __restrict__ bh0,
        const float* __restrict__ B1, const float* __restrict__ bi1, const float* __restrict__ bh1) {
    int dir = blockIdx.z;
    const float* B  = dir ? B1  : B0;
    const float* bi = dir ? bi1 : bi0;
    const float* bh = dir ? bh1 : bh0;
    float* C = g_pre + (size_t)dir * M640 * G4;

    __shared__ __align__(16) float As[16][128];
    __shared__ __align__(16) float Bs[16][64];

    int tid = threadIdx.x;
    int m0 = blockIdx.y * 128, n0 = blockIdx.x * 64;

    // loader roles: A thread (arow, ahalf) covers k in [ahalf*8, ahalf*8+8)
    int arow = tid & 127, ahalf = tid >> 7;
    int brow = tid & 63,  bq   = tid >> 6;
    const float* Ag; float sA = 1.f;
    {
        int m = m0 + arow;
        if (phase) {
            Ag = g_x1 + (size_t)m * DD;
        } else {
            int t = m / NB, b = m - NB * t;
            Ag = ep + ((size_t)g_idx[b] * NT + t) * DD;
            sA = g_wsel[b];
        }
    }
    const float* Bg = B + (size_t)(n0 + brow) * DD;

    // output roles: rows [tr*8,+8), cols [tc*4,+4)
    int tr = tid >> 4, tc = tid & 15;
    float2 accL[8], accH[8];
#pragma unroll
    for (int i = 0; i < 8; i++) { accL[i] = make_float2(0.f, 0.f); accH[i] = make_float2(0.f, 0.f); }

    // prefetch k0 = 0
    float4 pa0 = *(const float4*)(Ag + ahalf * 8);
    float4 pa1 = *(const float4*)(Ag + ahalf * 8 + 4);
    float4 pb  = *(const float4*)(Bg + bq * 4);

    for (int k0 = 0; k0 < DD; k0 += 16) {
        // commit prefetched tile to smem (scale A here)
        As[ahalf * 8 + 0][arow] = pa0.x * sA;
        As[ahalf * 8 + 1][arow] = pa0.y * sA;
        As[ahalf * 8 + 2][arow] = pa0.z * sA;
        As[ahalf * 8 + 3][arow] = pa0.w * sA;
        As[ahalf * 8 + 4][arow] = pa1.x * sA;
        As[ahalf * 8 + 5][arow] = pa1.y * sA;
        As[ahalf * 8 + 6][arow] = pa1.z * sA;
        As[ahalf * 8 + 7][arow] = pa1.w * sA;
        Bs[bq * 4 + 0][brow] = pb.x;
        Bs[bq * 4 + 1][brow] = pb.y;
        Bs[bq * 4 + 2][brow] = pb.z;
        Bs[bq * 4 + 3][brow] = pb.w;
        __syncthreads();

        // issue next tile's loads early (hidden under compute)
        if (k0 + 16 < DD) {
            pa0 = *(const float4*)(Ag + k0 + 16 + ahalf * 8);
            pa1 = *(const float4*)(Ag + k0 + 16 + ahalf * 8 + 4);
            pb  = *(const float4*)(Bg + k0 + 16 + bq * 4);
        }

#pragma unroll
        for (int kk = 0; kk < 16; kk++) {
            float4 a0 = *(const float4*)&As[kk][tr * 8];
            float4 a1 = *(const float4*)&As[kk][tr * 8 + 4];
            float4 b  = *(const float4*)&Bs[kk][tc * 4];
            float2 b01 = make_float2(b.x, b.y), b23 = make_float2(b.z, b.w);
            float aa[8] = { a0.x, a0.y, a0.z, a0.w, a1.x, a1.y, a1.z, a1.w };
#pragma unroll
            for (int i = 0; i < 8; i++) {
                float2 ad = make_float2(aa[i], aa[i]);
                accL[i] = f2fma(ad, b01, accL[i]);
                accH[i] = f2fma(ad, b23, accH[i]);
            }
        }
        __syncthreads();
    }

    int n = n0 + tc * 4;
    float bs0 = bi[n + 0] + bh[n + 0];
    float bs1 = bi[n + 1] + bh[n + 1];
    float bs2 = bi[n + 2] + bh[n + 2];
    float bs3 = bi[n + 3] + bh[n + 3];
#pragma unroll
    for (int i = 0; i < 8; i++) {
        int m = m0 + tr * 8 + i;
        float4 o;
        o.x = accL[i].x + bs0;
        o.y = accL[i].y + bs1;
        o.z = accH[i].x + bs2;
        o.w = accH[i].y + bs3;
        *(float4*)&C[(size_t)m * G4 + n] = o;
    }
}

// ---------------- bidirectional LSTM scan: tagged data-flow sync (R14) + fused act ----
// 64 persistent CTAs x 256 thr; CTA owns 8 hidden units (32 gate rows).
// warp = h-segment, lane = gate row, w_hh in registers.
// h exchange: {h, tag=s+1} as atomic 8B volatile stores; consumers poll
// their own element (x5 batches) until tag matches. Double-buffered by parity.
// red double-buffered by step parity; act threads sum partials directly
// (one __syncthreads per step, no garr).
__global__ void __launch_bounds__(256) k_scan(int phase,
        const float* __restrict__ whf, const float* __restrict__ whb) {
    float* out = phase ? g_lout : g_x1;
    int cta = blockIdx.x;
    int dir = cta >> 5;
    int gidx = cta & 31;
    int hbase = gidx * 8;
    const float* whh  = dir ? whb : whf;
    const float* preb = g_pre + (size_t)dir * M640 * G4;
    float2* hx = &g_hx[phase][dir][0][0][0];   // [parity][b][elem]

    int tid  = threadIdx.x;
    int wsg  = tid >> 5;     // h-segment 0..7
    int lane = tid & 31;     // gate row 0..31
    int jrow = (lane >> 3) * HH + hbase + (lane & 7);

    float2 wreg[16];
    {
        const float2* wr = (const float2*)(whh + (size_t)jrow * HH + wsg * 32);
#pragma unroll
        for (int i = 0; i < 16; i++) wreg[i] = wr[i];
    }

    __shared__ __align__(16) float hsp[NB][HH];     // staged h_{t-1} (warp-local regions)
    __shared__ float red[2][8][32][NB];             // parity-double-buffered partials

    bool isact = tid < 8 * NB;                      // activation role (tid<40)
    int u8 = tid / NB, b8 = tid - u8 * NB;
    int hg = hbase + u8;
    float cstate = 0.f;

    for (int s = 0; s < NT; s++) {
        int t = dir ? (NT - 1 - s) : s;
        int par = s & 1;

        // act threads prefetch their 4 pre-gate values (overlaps poll + matvec)
        float pg0 = 0.f, pg1 = 0.f, pg2 = 0.f, pg3 = 0.f;
        if (isact) {
            size_t base = ((size_t)t * NB + b8) * G4 + hg;
            pg0 = __ldg(preb + base);
            pg1 = __ldg(preb + base + 256);
            pg2 = __ldg(preb + base + 512);
            pg3 = __ldg(preb + base + 768);
        }

        float2 acc[NB];
#pragma unroll
        for (int b = 0; b < NB; b++) acc[b] = make_float2(0.f, 0.f);

        if (s > 0) {
            // poll own element (x5 batches) until tag == s (R14 protocol, no backoff)
            const float2* hb = hx + ((s - 1) & 1) * (NB * HH) + tid;
            float tagf = (float)s;
            float2 v0, v1, v2, v3, v4;
            for (;;) {
                v0 = ld_vol_f2(hb + 0 * HH);
                v1 = ld_vol_f2(hb + 1 * HH);
                v2 = ld_vol_f2(hb + 2 * HH);
                v3 = ld_vol_f2(hb + 3 * HH);
                v4 = ld_vol_f2(hb + 4 * HH);
                if (v0.y == tagf && v1.y == tagf && v2.y == tagf &&
                    v3.y == tagf && v4.y == tagf) break;
            }
            hsp[0][tid] = v0.x; hsp[1][tid] = v1.x; hsp[2][tid] = v2.x;
            hsp[3][tid] = v3.x; hsp[4][tid] = v4.x;
            __syncwarp();   // warp wsg's matvec uses exactly elements [32*wsg, +32)

#pragma unroll
            for (int i4 = 0; i4 < 8; i4++) {
                float2 w0 = wreg[2 * i4], w1 = wreg[2 * i4 + 1];
#pragma unroll
                for (int b = 0; b < NB; b++) {
                    float4 h = *(const float4*)&hsp[b][(wsg << 5) + (i4 << 2)]; // broadcast
                    acc[b] = f2fma(w0, make_float2(h.x, h.y), acc[b]);
                    acc[b] = f2fma(w1, make_float2(h.z, h.w), acc[b]);
                }
            }
        }
#pragma unroll
        for (int b = 0; b < NB; b++) red[par][wsg][lane][b] = acc[b].x + acc[b].y;
        __syncthreads();

        if (isact) {
            float ig = pg0, fg = pg1, cg = pg2, og = pg3;
#pragma unroll
            for (int q = 0; q < 8; q++) {
                ig += red[par][q][u8][b8];
                fg += red[par][q][8 + u8][b8];
                cg += red[par][q][16 + u8][b8];
                og += red[par][q][24 + u8][b8];
            }
            float si = fast_sigmoid(ig);
            float sf = fast_sigmoid(fg);
            float so = fast_sigmoid(og);
            cstate = sf * cstate + si * fast_tanh(cg);
            float hv = so * fast_tanh(cstate);
            out[((size_t)t * NB + b8) * DD + dir * HH + hg] = hv;
            if (s < NT - 1)
                st_vol_f2(hx + (s & 1) * (NB * HH) + b8 * HH + hg, hv, (float)(s + 1));
        }
        // no trailing barrier: red is parity-double-buffered; reuse of red[par]
        // at step s+2 is ordered behind this act's reads via the s+1 barrier.
    }
}

// ---------------- attention + softmax + context ----------------
__global__ void k_attn(const float* __restrict__ cs, float* __restrict__ outp) {
    __shared__ __align__(16) float css[DD];
    __shared__ float aw[NT];
    __shared__ float r1[NT];
    int b = blockIdx.x, tid = threadIdx.x;
    ((float4*)css)[tid] = ((const float4*)cs)[tid];
    __syncthreads();

    const float4* lb = (const float4*)(g_lout + ((size_t)tid * NB + b) * DD);
    float att = 0.f;
#pragma unroll 4
    for (int i = 0; i < DD / 4; i++) {
        float4 x = lb[i];
        float4 c = ((float4*)css)[i];
        att += x.x * c.x + x.y * c.y + x.z * c.z + x.w * c.w;
    }
    r1[tid] = att;
    __syncthreads();
    for (int st = 64; st > 0; st >>= 1) {
        if (tid < st) r1[tid] = fmaxf(r1[tid], r1[tid + st]);
        __syncthreads();
    }
    float mx = r1[0];
    __syncthreads();
    float e = expf(att - mx);
    r1[tid] = e;
    __syncthreads();
    for (int st = 64; st > 0; st >>= 1) {
        if (tid < st) r1[tid] += r1[tid + st];
        __syncthreads();
    }
    float inv = 1.f / r1[0];
    __syncthreads();
    aw[tid] = e * inv;
    __syncthreads();

    float4 ctx = make_float4(0.f, 0.f, 0.f, 0.f);
    for (int l = 0; l < NT; l++) {
        float wv = aw[l];
        float4 x = *(const float4*)(g_lout + ((size_t)l * NB + b) * DD + (tid << 2));
        ctx.x += wv * x.x; ctx.y += wv * x.y; ctx.z += wv * x.z; ctx.w += wv * x.w;
    }
    *(float4*)(outp + (size_t)b * DD + (tid << 2)) = ctx;
}

// ---------------- launcher (scan0 is launch #4 -> ncu captures it) ----------------
extern "C" void kernel_launch(void* const* d_in, const int* in_sizes, int n_in,
                              void* d_out, int out_size) {
    const float* episodes = (const float*)d_in[0];
    const float* query    = (const float*)d_in[1];
    const float* cstate   = (const float*)d_in[2];
    const float* ages     = (const float*)d_in[3];
    const float* Wq = (const float*)d_in[4];
    const float* bq = (const float*)d_in[5];
    const float* Wk = (const float*)d_in[6];
    const float* bk = (const float*)d_in[7];
    const float* w_ih_l0  = (const float*)d_in[8];
    const float* w_hh_l0  = (const float*)d_in[9];
    const float* b_ih_l0  = (const float*)d_in[10];
    const float* b_hh_l0  = (const float*)d_in[11];
    const float* w_ih_l0r = (const float*)d_in[12];
    const float* w_hh_l0r = (const float*)d_in[13];
    const float* b_ih_l0r = (const float*)d_in[14];
    const float* b_hh_l0r = (const float*)d_in[15];
    const float* w_ih_l1  = (const float*)d_in[16];
    const float* w_hh_l1  = (const float*)d_in[17];
    const float* b_ih_l1  = (const float*)d_in[18];
    const float* b_hh_l1  = (const float*)d_in[19];
    const float* w_ih_l1r = (const float*)d_in[20];
    const float* w_hh_l1r = (const float*)d_in[21];
    const float* b_ih_l1r = (const float*)d_in[22];
    const float* b_hh_l1r = (const float*)d_in[23];
    float* out = (float*)d_out;

    k_prep       <<<1, 512>>>(query, Wq, bq, Wk, bk);                     // 1
    k_scores_topk<<<NEP, 256>>>(episodes, ages);                          // 2
    k_gemm<<<dim3(16, 5, 2), 256>>>(0, episodes,                          // 3
                                    w_ih_l0, b_ih_l0, b_hh_l0,
                                    w_ih_l0r, b_ih_l0r, b_hh_l0r);
    k_scan<<<SCTA, 256>>>(0, w_hh_l0, w_hh_l0r);                          // 4 <- ncu capture
    k_gemm<<<dim3(16, 5, 2), 256>>>(1, episodes,                          // 5
                                    w_ih_l1, b_ih_l1, b_hh_l1,
                                    w_ih_l1r, b_ih_l1r, b_hh_l1r);
    k_scan<<<SCTA, 256>>>(1, w_hh_l1, w_hh_l1r);                          // 6
    k_attn<<<NB, 128>>>(cstate, out);                                     // 7
}

// round 17
// speedup vs baseline: 1.1241x; 1.0358x over previous
#include <cuda_runtime.h>
#include <math.h>

#define DD    512
#define HH    256
#define G4    1024
#define NT    128
#define NB    5
#define NEP   1024
#define M640  640      // NT*NB
#define SCTA  64       // scan CTAs (32 per direction)

// ---------- static device scratch (no allocation) ----------
__device__ __align__(16) float g_v[DD];
__device__ float g_c0;
__device__ __align__(16) float g_scores[NEP];
__device__ int   g_idx[8];
__device__ float g_wsel[8];
__device__ __align__(16) float g_x1 [M640 * DD];       // layer-0 output
__device__ __align__(16) float g_lout[M640 * DD];      // layer-1 output
__device__ __align__(16) float g_pre[2 * M640 * G4];   // pre-gates [dir][m][j]
// tagged h exchange: [phase][dir][parity][b][elem] = {h, tag}; tag = step+1 (never 0)
__device__ __align__(16) float2 g_hx[2][2][2][NB][HH];
__device__ unsigned g_done;    // scores->topk last-block counter (self-resetting)

// ---------- helpers ----------
union F2U { float2 f; unsigned long long u; };
__device__ __forceinline__ float2 f2fma(float2 a, float2 b, float2 c) {
    F2U A, B, C, Dv; A.f = a; B.f = b; C.f = c;
    asm("fma.rn.f32x2 %0, %1, %2, %3;" : "=l"(Dv.u) : "l"(A.u), "l"(B.u), "l"(C.u));
    return Dv.f;
}
__device__ __forceinline__ float fast_tanh(float x) {
    float r; asm("tanh.approx.f32 %0, %1;" : "=f"(r) : "f"(x)); return r;
}
// sigmoid(x) = 0.5*tanh(0.5x) + 0.5  (one MUFU instead of EX2+RCP chain)
__device__ __forceinline__ float fast_sigmoid(float x) {
    return fmaf(0.5f, fast_tanh(0.5f * x), 0.5f);
}
__device__ __forceinline__ float2 ld_vol_f2(const float2* p) {
    float2 v;
    asm volatile("ld.volatile.global.v2.f32 {%0,%1}, [%2];"
                 : "=f"(v.x), "=f"(v.y) : "l"(p) : "memory");
    return v;
}
__device__ __forceinline__ void st_vol_f2(float2* p, float h, float tag) {
    asm volatile("st.volatile.global.v2.f32 [%0], {%1,%2};"
                 :: "l"(p), "f"(h), "f"(tag) : "memory");
}

// ---------------- qp = Wq@q + bq ; v = Wk^T@qp ; c0 = bk.qp ----------------
__global__ void k_prep(const float* __restrict__ query, const float* __restrict__ Wq,
                       const float* __restrict__ bq, const float* __restrict__ Wk,
                       const float* __restrict__ bk) {
    __shared__ float qs[DD], qps[DD], red[DD];
    int tid = threadIdx.x;
    qs[tid] = query[tid];
    __syncthreads();
    const float* wr = Wq + (size_t)tid * DD;
    float s = bq[tid];
#pragma unroll 8
    for (int d = 0; d < DD; d++) s += wr[d] * qs[d];
    qps[tid] = s;
    __syncthreads();
    float vv = 0.f;
#pragma unroll 8
    for (int e = 0; e < DD; e++) vv += Wk[(size_t)e * DD + tid] * qps[e];
    g_v[tid] = vv;
    red[tid] = bk[tid] * qps[tid];
    __syncthreads();
    for (int st = 256; st > 0; st >>= 1) {
        if (tid < st) red[tid] += red[tid + st];
        __syncthreads();
    }
    if (tid == 0) g_c0 = red[0];
}

// ---------------- fused scores + top-5 (last block does topk) ----------------
__global__ void __launch_bounds__(256) k_scores_topk(const float* __restrict__ ep,
                                                     const float* __restrict__ ages) {
    __shared__ float4 vs[DD / 4];
    __shared__ float sred[256];
    __shared__ int s_last;
    int tid = threadIdx.x;
    if (tid < 128) vs[tid] = ((const float4*)g_v)[tid];
    __syncthreads();
    const float4* e4 = (const float4*)ep + (size_t)blockIdx.x * (NT * DD / 4);
    float acc = 0.f;
#pragma unroll 4
    for (int it = 0; it < 64; it++) {
        int i = tid + 256 * it;
        float4 x = e4[i];
        float4 w = vs[i & 127];
        acc += x.x * w.x + x.y * w.y + x.z * w.z + x.w * w.w;
    }
    sred[tid] = acc;
    __syncthreads();
    for (int st = 128; st > 0; st >>= 1) {
        if (tid < st) sred[tid] += sred[tid + st];
        __syncthreads();
    }
    if (tid == 0) {
        g_scores[blockIdx.x] = sred[0] * (1.0f / NT) + g_c0;
        __threadfence();
        unsigned old = atomicAdd(&g_done, 1u);
        s_last = (old == NEP - 1u) ? 1 : 0;
    }
    __syncthreads();
    if (!s_last) return;

    __shared__ float sc[NEP];
    __shared__ float wv_[8];
    __shared__ int   wi_[8];
    int lane = tid & 31, wid = tid >> 5;
    __threadfence();
    for (int i = tid; i < NEP; i += 256) sc[i] = g_scores[i];
    __syncthreads();
    for (int r = 0; r < NB; r++) {
        float bv = -INFINITY; int bi = 0x7fffffff;
        for (int i = tid; i < NEP; i += 256) {
            float v = sc[i];
            if (v > bv || (v == bv && i < bi)) { bv = v; bi = i; }
        }
#pragma unroll
        for (int off = 16; off; off >>= 1) {
            float ov = __shfl_down_sync(0xffffffffu, bv, off);
            int   oi = __shfl_down_sync(0xffffffffu, bi, off);
            if (ov > bv || (ov == bv && oi < bi)) { bv = ov; bi = oi; }
        }
        if (lane == 0) { wv_[wid] = bv; wi_[wid] = bi; }
        __syncthreads();
        if (tid < 8) {
            bv = wv_[tid]; bi = wi_[tid];
#pragma unroll
            for (int off = 4; off; off >>= 1) {
                float ov = __shfl_down_sync(0xffu, bv, off);
                int   oi = __shfl_down_sync(0xffu, bi, off);
                if (ov > bv || (ov == bv && oi < bi)) { bv = ov; bi = oi; }
            }
            if (tid == 0) {
                g_idx[r]  = bi;
                g_wsel[r] = 1.f / (1.f + ages[bi] * 0.01f);
                sc[bi] = -INFINITY;
            }
        }
        __syncthreads();
    }
    if (tid == 0) g_done = 0u;                 // self-reset for graph replay
}

// ---------------- pre-gate GEMM: 128x64 tile, 8x4/thread, COALESCED loaders ----
// grid (16 nTiles, 5 mTiles, 2 dir) x 256. phase 0 fuses the episode gather+scale.
// A loader: arow=tid>>1, ahalf=tid&1 -> 64B contiguous runs per row per warp.
// B loader: brow=tid>>2, bq=tid&3    -> 64B contiguous runs per row per warp.
__global__ void __launch_bounds__(256) k_gemm(int phase, const float* __restrict__ ep,
        const float* __restrict__ B0, const float* __restrict__ bi0, const float* __restrict__ bh0,
        const float* __restrict__ B1, const float* __restrict__ bi1, const float* __restrict__ bh1) {
    int dir = blockIdx.z;
    const float* B  = dir ? B1  : B0;
    const float* bi = dir ? bi1 : bi0;
    const float* bh = dir ? bh1 : bh0;
    float* C = g_pre + (size_t)dir * M640 * G4;

    __shared__ __align__(16) float As[16][128];
    __shared__ __align__(16) float Bs[16][64];

    int tid = threadIdx.x;
    int m0 = blockIdx.y * 128, n0 = blockIdx.x * 64;

    // coalesced loader roles
    int arow = tid >> 1, ahalf = tid & 1;    // A: k in [ahalf*8, +8)
    int brow = tid >> 2, bq   = tid & 3;     // B: k in [bq*4, +4)
    const float* Ag; float sA = 1.f;
    {
        int m = m0 + arow;
        if (phase) {
            Ag = g_x1 + (size_t)m * DD;
        } else {
            int t = m / NB, b = m - NB * t;
            Ag = ep + ((size_t)g_idx[b] * NT + t) * DD;
            sA = g_wsel[b];
        }
    }
    const float* Bg = B + (size_t)(n0 + brow) * DD;

    // output roles: rows [tr*8,+8), cols [tc*4,+4)
    int tr = tid >> 4, tc = tid & 15;
    float2 accL[8], accH[8];
#pragma unroll
    for (int i = 0; i < 8; i++) { accL[i] = make_float2(0.f, 0.f); accH[i] = make_float2(0.f, 0.f); }

    // prefetch k0 = 0
    float4 pa0 = *(const float4*)(Ag + ahalf * 8);
    float4 pa1 = *(const float4*)(Ag + ahalf * 8 + 4);
    float4 pb  = *(const float4*)(Bg + bq * 4);

    for (int k0 = 0; k0 < DD; k0 += 16) {
        // commit prefetched tile to smem (scale A here)
        As[ahalf * 8 + 0][arow] = pa0.x * sA;
        As[ahalf * 8 + 1][arow] = pa0.y * sA;
        As[ahalf * 8 + 2][arow] = pa0.z * sA;
        As[ahalf * 8 + 3][arow] = pa0.w * sA;
        As[ahalf * 8 + 4][arow] = pa1.x * sA;
        As[ahalf * 8 + 5][arow] = pa1.y * sA;
        As[ahalf * 8 + 6][arow] = pa1.z * sA;
        As[ahalf * 8 + 7][arow] = pa1.w * sA;
        Bs[bq * 4 + 0][brow] = pb.x;
        Bs[bq * 4 + 1][brow] = pb.y;
        Bs[bq * 4 + 2][brow] = pb.z;
        Bs[bq * 4 + 3][brow] = pb.w;
        __syncthreads();

        // issue next tile's loads early (hidden under compute)
        if (k0 + 16 < DD) {
            pa0 = *(const float4*)(Ag + k0 + 16 + ahalf * 8);
            pa1 = *(const float4*)(Ag + k0 + 16 + ahalf * 8 + 4);
            pb  = *(const float4*)(Bg + k0 + 16 + bq * 4);
        }

#pragma unroll
        for (int kk = 0; kk < 16; kk++) {
            float4 a0 = *(const float4*)&As[kk][tr * 8];
            float4 a1 = *(const float4*)&As[kk][tr * 8 + 4];
            float4 b  = *(const float4*)&Bs[kk][tc * 4];
            float2 b01 = make_float2(b.x, b.y), b23 = make_float2(b.z, b.w);
            float aa[8] = { a0.x, a0.y, a0.z, a0.w, a1.x, a1.y, a1.z, a1.w };
#pragma unroll
            for (int i = 0; i < 8; i++) {
                float2 ad = make_float2(aa[i], aa[i]);
                accL[i] = f2fma(ad, b01, accL[i]);
                accH[i] = f2fma(ad, b23, accH[i]);
            }
        }
        __syncthreads();
    }

    int n = n0 + tc * 4;
    float bs0 = bi[n + 0] + bh[n + 0];
    float bs1 = bi[n + 1] + bh[n + 1];
    float bs2 = bi[n + 2] + bh[n + 2];
    float bs3 = bi[n + 3] + bh[n + 3];
#pragma unroll
    for (int i = 0; i < 8; i++) {
        int m = m0 + tr * 8 + i;
        float4 o;
        o.x = accL[i].x + bs0;
        o.y = accL[i].y + bs1;
        o.z = accH[i].x + bs2;
        o.w = accH[i].y + bs3;
        *(float4*)&C[(size_t)m * G4 + n] = o;
    }
}

// ---------------- bidirectional LSTM scan: tagged data-flow sync + fused act ----
// (unchanged from R16: 182.5 us measured)
__global__ void __launch_bounds__(256) k_scan(int phase,
        const float* __restrict__ whf, const float* __restrict__ whb) {
    float* out = phase ? g_lout : g_x1;
    int cta = blockIdx.x;
    int dir = cta >> 5;
    int gidx = cta & 31;
    int hbase = gidx * 8;
    const float* whh  = dir ? whb : whf;
    const float* preb = g_pre + (size_t)dir * M640 * G4;
    float2* hx = &g_hx[phase][dir][0][0][0];   // [parity][b][elem]

    int tid  = threadIdx.x;
    int wsg  = tid >> 5;     // h-segment 0..7
    int lane = tid & 31;     // gate row 0..31
    int jrow = (lane >> 3) * HH + hbase + (lane & 7);

    float2 wreg[16];
    {
        const float2* wr = (const float2*)(whh + (size_t)jrow * HH + wsg * 32);
#pragma unroll
        for (int i = 0; i < 16; i++) wreg[i] = wr[i];
    }

    __shared__ __align__(16) float hsp[NB][HH];     // staged h_{t-1} (warp-local regions)
    __shared__ float red[2][8][32][NB];             // parity-double-buffered partials

    bool isact = tid < 8 * NB;                      // activation role (tid<40)
    int u8 = tid / NB, b8 = tid - u8 * NB;
    int hg = hbase + u8;
    float cstate = 0.f;

    for (int s = 0; s < NT; s++) {
        int t = dir ? (NT - 1 - s) : s;
        int par = s & 1;

        // act threads prefetch their 4 pre-gate values (overlaps poll + matvec)
        float pg0 = 0.f, pg1 = 0.f, pg2 = 0.f, pg3 = 0.f;
        if (isact) {
            size_t base = ((size_t)t * NB + b8) * G4 + hg;
            pg0 = __ldg(preb + base);
            pg1 = __ldg(preb + base + 256);
            pg2 = __ldg(preb + base + 512);
            pg3 = __ldg(preb + base + 768);
        }

        float2 acc[NB];
#pragma unroll
        for (int b = 0; b < NB; b++) acc[b] = make_float2(0.f, 0.f);

        if (s > 0) {
            // poll own element (x5 batches) until tag == s (R14 protocol, no backoff)
            const float2* hb = hx + ((s - 1) & 1) * (NB * HH) + tid;
            float tagf = (float)s;
            float2 v0, v1, v2, v3, v4;
            for (;;) {
                v0 = ld_vol_f2(hb + 0 * HH);
                v1 = ld_vol_f2(hb + 1 * HH);
                v2 = ld_vol_f2(hb + 2 * HH);
                v3 = ld_vol_f2(hb + 3 * HH);
                v4 = ld_vol_f2(hb + 4 * HH);
                if (v0.y == tagf && v1.y == tagf && v2.y == tagf &&
                    v3.y == tagf && v4.y == tagf) break;
            }
            hsp[0][tid] = v0.x; hsp[1][tid] = v1.x; hsp[2][tid] = v2.x;
            hsp[3][tid] = v3.x; hsp[4][tid] = v4.x;
            __syncwarp();   // warp wsg's matvec uses exactly elements [32*wsg, +32)

#pragma unroll
            for (int i4 = 0; i4 < 8; i4++) {
                float2 w0 = wreg[2 * i4], w1 = wreg[2 * i4 + 1];
#pragma unroll
                for (int b = 0; b < NB; b++) {
                    float4 h = *(const float4*)&hsp[b][(wsg << 5) + (i4 << 2)]; // broadcast
                    acc[b] = f2fma(w0, make_float2(h.x, h.y), acc[b]);
                    acc[b] = f2fma(w1, make_float2(h.z, h.w), acc[b]);
                }
            }
        }
#pragma unroll
        for (int b = 0; b < NB; b++) red[par][wsg][lane][b] = acc[b].x + acc[b].y;
        __syncthreads();

        if (isact) {
            float ig = pg0, fg = pg1, cg = pg2, og = pg3;
#pragma unroll
            for (int q = 0; q < 8; q++) {
                ig += red[par][q][u8][b8];
                fg += red[par][q][8 + u8][b8];
                cg += red[par][q][16 + u8][b8];
                og += red[par][q][24 + u8][b8];
            }
            float si = fast_sigmoid(ig);
            float sf = fast_sigmoid(fg);
            float so = fast_sigmoid(og);
            cstate = sf * cstate + si * fast_tanh(cg);
            float hv = so * fast_tanh(cstate);
            out[((size_t)t * NB + b8) * DD + dir * HH + hg] = hv;
            if (s < NT - 1)
                st_vol_f2(hx + (s & 1) * (NB * HH) + b8 * HH + hg, hv, (float)(s + 1));
        }
        // no trailing barrier: red is parity-double-buffered; reuse of red[par]
        // at step s+2 is ordered behind this act's reads via the s+1 barrier.
    }
}

// ---------------- attention + softmax + context ----------------
__global__ void k_attn(const float* __restrict__ cs, float* __restrict__ outp) {
    __shared__ __align__(16) float css[DD];
    __shared__ float aw[NT];
    __shared__ float r1[NT];
    int b = blockIdx.x, tid = threadIdx.x;
    ((float4*)css)[tid] = ((const float4*)cs)[tid];
    __syncthreads();

    const float4* lb = (const float4*)(g_lout + ((size_t)tid * NB + b) * DD);
    float att = 0.f;
#pragma unroll 4
    for (int i = 0; i < DD / 4; i++) {
        float4 x = lb[i];
        float4 c = ((float4*)css)[i];
        att += x.x * c.x + x.y * c.y + x.z * c.z + x.w * c.w;
    }
    r1[tid] = att;
    __syncthreads();
    for (int st = 64; st > 0; st >>= 1) {
        if (tid < st) r1[tid] = fmaxf(r1[tid], r1[tid + st]);
        __syncthreads();
    }
    float mx = r1[0];
    __syncthreads();
    float e = expf(att - mx);
    r1[tid] = e;
    __syncthreads();
    for (int st = 64; st > 0; st >>= 1) {
        if (tid < st) r1[tid] += r1[tid + st];
        __syncthreads();
    }
    float inv = 1.f / r1[0];
    __syncthreads();
    aw[tid] = e * inv;
    __syncthreads();

    float4 ctx = make_float4(0.f, 0.f, 0.f, 0.f);
    for (int l = 0; l < NT; l++) {
        float wv = aw[l];
        float4 x = *(const float4*)(g_lout + ((size_t)l * NB + b) * DD + (tid << 2));
        ctx.x += wv * x.x; ctx.y += wv * x.y; ctx.z += wv * x.z; ctx.w += wv * x.w;
    }
    *(float4*)(outp + (size_t)b * DD + (tid << 2)) = ctx;
}

// ---------------- launcher (scan0 is launch #4 -> ncu captures it) ----------------
extern "C" void kernel_launch(void* const* d_in, const int* in_sizes, int n_in,
                              void* d_out, int out_size) {
    const float* episodes = (const float*)d_in[0];
    const float* query    = (const float*)d_in[1];
    const float* cstate   = (const float*)d_in[2];
    const float* ages     = (const float*)d_in[3];
    const float* Wq = (const float*)d_in[4];
    const float* bq = (const float*)d_in[5];
    const float* Wk = (const float*)d_in[6];
    const float* bk = (const float*)d_in[7];
    const float* w_ih_l0  = (const float*)d_in[8];
    const float* w_hh_l0  = (const float*)d_in[9];
    const float* b_ih_l0  = (const float*)d_in[10];
    const float* b_hh_l0  = (const float*)d_in[11];
    const float* w_ih_l0r = (const float*)d_in[12];
    const float* w_hh_l0r = (const float*)d_in[13];
    const float* b_ih_l0r = (const float*)d_in[14];
    const float* b_hh_l0r = (const float*)d_in[15];
    const float* w_ih_l1  = (const float*)d_in[16];
    const float* w_hh_l1  = (const float*)d_in[17];
    const float* b_ih_l1  = (const float*)d_in[18];
    const float* b_hh_l1  = (const float*)d_in[19];
    const float* w_ih_l1r = (const float*)d_in[20];
    const float* w_hh_l1r = (const float*)d_in[21];
    const float* b_ih_l1r = (const float*)d_in[22];
    const float* b_hh_l1r = (const float*)d_in[23];
    float* out = (float*)d_out;

    k_prep       <<<1, 512>>>(query, Wq, bq, Wk, bk);                     // 1
    k_scores_topk<<<NEP, 256>>>(episodes, ages);                          // 2
    k_gemm<<<dim3(16, 5, 2), 256>>>(0, episodes,                          // 3
                                    w_ih_l0, b_ih_l0, b_hh_l0,
                                    w_ih_l0r, b_ih_l0r, b_hh_l0r);
    k_scan<<<SCTA, 256>>>(0, w_hh_l0, w_hh_l0r);                          // 4 <- ncu capture
    k_gemm<<<dim3(16, 5, 2), 256>>>(1, episodes,                          // 5
                                    w_ih_l1, b_ih_l1, b_hh_l1,
                                    w_ih_l1r, b_ih_l1r, b_hh_l1r);
    k_scan<<<SCTA, 256>>>(1, w_hh_l1, w_hh_l1r);                          // 6
    k_attn<<<NB, 128>>>(cstate, out);                                     // 7
}